// round 4
// baseline (speedup 1.0000x reference)
#include <cuda_runtime.h>
#include <cstdint>

typedef unsigned long long ull;

#define Bb 2048
#define Tt 1000
#define Ii 40
#define Hh 16
#define TS 20
#define NCH (Tt/TS)
#define PADF 8
#define BSTR (TS*Ii + PADF)     /* 808 floats per chunk slot (16B aligned stride) */

// -------- device-global scratch (no allocation allowed) --------
__device__ float2 g_wp[32*20];       // per neuron-branch nb: 20 dense weight pairs, pre-scaled by (1-a)(1-b)
__device__ float  g_alpha2[32];      // alpha[h] replicated per branch lane
__device__ float  g_betab[32];       // beta per neuron-branch
__device__ float2 g_w2[Hh];          // (W2[0][h], W2[1][h])
__device__ float2 g_b2c;
__device__ uint32_t g_masks[Bb*Tt];  // per (b,t) 32-bit ballot (adjacent bits duplicated)

// -------- packed f32x2 helpers --------
__device__ __forceinline__ ull pk2(float a, float b){ ull r; asm("mov.b64 %0,{%1,%2};":"=l"(r):"f"(a),"f"(b)); return r; }
__device__ __forceinline__ void upk2(ull v, float&a, float&b){ asm("mov.b64 {%0,%1},%2;":"=f"(a),"=f"(b):"l"(v)); }
__device__ __forceinline__ ull fma2(ull a, ull b, ull c){ ull d; asm("fma.rn.f32x2 %0,%1,%2,%3;":"=l"(d):"l"(a),"l"(b),"l"(c)); return d; }
__device__ __forceinline__ ull mul2(ull a, ull b){ ull d; asm("mul.rn.f32x2 %0,%1,%2;":"=l"(d):"l"(a),"l"(b)); return d; }
__device__ __forceinline__ ull add2(ull a, ull b){ ull d; asm("add.rn.f32x2 %0,%1,%2;":"=l"(d):"l"(a),"l"(b)); return d; }
// non-volatile: let ptxas software-pipeline loads across timesteps
__device__ __forceinline__ void lds128(uint32_t a, ull&u, ull&v){ asm("ld.shared.v2.b64 {%0,%1},[%2];":"=l"(u),"=l"(v):"r"(a)); }
__device__ __forceinline__ void cpa16(uint32_t d, const void* s){ asm volatile("cp.async.cg.shared.global [%0],[%1],16;"::"r"(d),"l"(s)); }
__device__ __forceinline__ void cp_commit(){ asm volatile("cp.async.commit_group;"); }
__device__ __forceinline__ void stg32_lane0(int lane, uint32_t* p, uint32_t v){
  asm volatile("{ .reg .pred q; setp.eq.s32 q,%0,0; @q st.global.b32 [%1],%2; }"
               :: "r"(lane), "l"(p), "r"(v) : "memory");
}

// ---------------- prep: pack + pre-scale weights (parallel), init scalar outputs ----------------
__global__ void prep_kernel(const float* __restrict__ W1, const float* __restrict__ tau_m,
                            const float* __restrict__ tau_n, const float* __restrict__ mask,
                            const float* __restrict__ W2, const float* __restrict__ b2,
                            float* __restrict__ out, long long corrIdx, long long totIdx){
  int tid = threadIdx.x;                    // 640 threads: (nb, k) pairs
  if (tid < 32*20){
    int nb = tid / 20, k = tid % 20;
    int h = nb >> 1;
    float a  = 1.0f/(1.0f + expf(-tau_m[h]));
    float be = 1.0f/(1.0f + expf(-tau_n[nb]));
    float s  = (1.0f - a)*(1.0f - be);      // fold (1-alpha)(1-beta) into weights
    int r = nb*Ii;
    g_wp[tid] = make_float2(W1[r+2*k]*mask[r+2*k]*s, W1[r+2*k+1]*mask[r+2*k+1]*s);
    if (k == 0){
      g_alpha2[nb] = a;
      g_betab[nb]  = be;
      if ((nb & 1) == 0) g_w2[h] = make_float2(W2[h], W2[Hh+h]);
    }
  }
  if (tid == 0){
    g_b2c = make_float2(b2[0], b2[1]);
    out[0] = 0.0f;
    out[corrIdx] = 0.0f;
    int cnt = 0;
    for (int t=0;t<Tt;t++) cnt += ((t>10) && (((t-10)%15)>5)) ? 1 : 0;
    out[totIdx] = (float)cnt * (float)Bb;   // flags.sum() * B
  }
}

// ---------------- main: warp = 1 batch, lane = neuron-branch (16 x 2) ----------------
// Per step/lane: dense 40-wide dot for ONE branch = 10 LDS.128 (pure broadcast) + 20 FFMA2 (2 chains),
// d' = beta*d' + c ; l = d' + shfl_xor(d',1) ; mem = alpha*mem + l - asel_prev ; spike = mem > 1.
__global__ void __launch_bounds__(32) snn_kernel(const float* __restrict__ x){
  __shared__ __align__(16) float sx[2*BSTR];
  const int lane = threadIdx.x;            // nb = 2h + br
  const int b    = blockIdx.x;

  ull w[20];
  #pragma unroll
  for (int k=0;k<20;k++){ float2 ww = g_wp[lane*20+k]; w[k]=pk2(ww.x,ww.y); }
  const float alpha = g_alpha2[lane];
  const float beta  = g_betab[lane];

  float d=0.f, mem=0.f, asel=0.f;
  uint32_t sbase = (uint32_t)__cvta_generic_to_shared(sx);
  uint32_t* mrow = g_masks + (size_t)b * Tt;
  const float4* xg = (const float4*)x + (size_t)b * Tt * 10;   // 40 f32 = 10 float4/step

  // stage chunk 0 (200 float4)
  for (int j=lane;j<200;j+=32) cpa16(sbase + (uint32_t)j*16u, xg + j);
  cp_commit();

  int buf = 0;
  for (int c=0;c<NCH;c++){
    if (c+1 < NCH){
      uint32_t sb = sbase + (uint32_t)((buf^1)*BSTR)*4u;
      const float4* p = xg + (size_t)(c+1)*200;
      for (int j=lane;j<200;j+=32) cpa16(sb + (uint32_t)j*16u, p + j);
      cp_commit();
      asm volatile("cp.async.wait_group 1;" ::: "memory");
    } else {
      asm volatile("cp.async.wait_group 0;" ::: "memory");
    }
    __syncwarp();

    uint32_t xaddr = sbase + (uint32_t)(buf*BSTR)*4u;

    #pragma unroll 4
    for (int tt=0; tt<TS; tt++){
      // dense dot, one branch: 10 LDS.128 broadcast -> 20 pairs, 2 FFMA2 chains
      ull pa, pb;
      lds128(xaddr, pa, pb);
      ull a0 = mul2(w[0], pa), a1 = mul2(w[1], pb);
      #pragma unroll
      for (int j=1;j<10;j++){
        ull xa, xb;
        lds128(xaddr + 16u*j, xa, xb);
        a0 = fma2(w[2*j],   xa, a0);
        a1 = fma2(w[2*j+1], xb, a1);
      }
      float f0,f1;
      ull s = add2(a0,a1); upk2(s,f0,f1);
      float cdot = f0+f1;                       // pre-scaled by (1-a)(1-b)

      d = fmaf(beta, d, cdot);                  // branch state
      float l = d + __shfl_xor_sync(0xffffffffu, d, 1);   // sum both branches
      mem = fmaf(alpha, mem, l) - asel;
      bool sp = mem > 1.0f;
      asel = sp ? alpha : 0.0f;                 // next-step reset term (off critical path)
      uint32_t m = __ballot_sync(0xffffffffu, sp);
      stg32_lane0(lane, mrow + tt, m);

      xaddr += Ii*4;
    }
    mrow += TS;
    __syncwarp();
    buf ^= 1;
  }
}

// ---------------- logits + loss + accuracy from spike masks (fully parallel) ----------------
// mask bits: neuron h spike at bit 2h (and duplicated at 2h+1).
__global__ void loss_kernel(const int* __restrict__ target, float* __restrict__ out,
                            long long corrIdx){
  // 4 LUTs: byte q of the mask (bits 8q..8q+7 -> neurons 4q..4q+3 at even bit positions)
  __shared__ float2 lut[4][256];
  for (int m = threadIdx.x; m < 256; m += blockDim.x){
    #pragma unroll
    for (int q=0;q<4;q++){
      float2 a = make_float2(0.f,0.f);
      #pragma unroll
      for (int j=0;j<4;j++){
        if ((m>>(2*j))&1){ float2 v = g_w2[4*q+j]; a.x += v.x; a.y += v.y; }
      }
      lut[q][m] = a;
    }
  }
  __syncthreads();

  int idx = blockIdx.x * blockDim.x + threadIdx.x;
  float lossv = 0.f, corr = 0.f;
  if (idx < Bb*Tt){
    int t = idx % Tt;
    uint32_t w32 = g_masks[idx];
    float2 c0 = lut[0][w32 & 0xFF];
    float2 c1 = lut[1][(w32>>8) & 0xFF];
    float2 c2 = lut[2][(w32>>16) & 0xFF];
    float2 c3 = lut[3][(w32>>24) & 0xFF];
    float2 b2v = g_b2c;
    float z0 = ((c0.x+c1.x)+(c2.x+c3.x)) + b2v.x;
    float z1 = ((c0.y+c1.y)+(c2.y+c3.y)) + b2v.y;
    out[1 + 2*(size_t)idx]     = z0;
    out[1 + 2*(size_t)idx + 1] = z1;
    if ((t>10) && (((t-10)%15)>5)){
      int tgt = target[idx];
      float mz = fmaxf(z0,z1);
      float q0 = __expf(z0-mz), q1 = __expf(z1-mz);
      float r  = 1.0f/(q0+q1);
      float p0 = q0*r, p1 = q1*r;                        // softmax(logits)
      float M  = fmaxf(p0,p1);
      float lse = M + __logf(__expf(p0-M)+__expf(p1-M)); // log-sum-exp of p (double softmax)
      lossv = (lse - ((tgt==0)?p0:p1)) * (1.0f/(float)Bb);
      corr  = ((((p1>p0)?1:0)==tgt)) ? 1.0f : 0.0f;
    }
  }
  #pragma unroll
  for (int off=16; off; off>>=1){
    lossv += __shfl_xor_sync(0xffffffffu, lossv, off);
    corr  += __shfl_xor_sync(0xffffffffu, corr,  off);
  }
  __shared__ float sl[32], sc[32];
  int w = threadIdx.x>>5, ln = threadIdx.x&31;
  if (ln==0){ sl[w]=lossv; sc[w]=corr; }
  __syncthreads();
  if (w==0){
    int nw = blockDim.x>>5;
    lossv = (ln<nw)? sl[ln]:0.f;
    corr  = (ln<nw)? sc[ln]:0.f;
    #pragma unroll
    for (int off=4; off; off>>=1){
      lossv += __shfl_xor_sync(0xffffffffu,lossv,off);
      corr  += __shfl_xor_sync(0xffffffffu,corr, off);
    }
    if (ln==0){ atomicAdd(out, lossv); atomicAdd(out+corrIdx, corr); }
  }
}

extern "C" void kernel_launch(void* const* d_in, const int* in_sizes, int n_in,
                              void* d_out, int out_size){
  const float* x      = (const float*)d_in[0];
  const int*   target = (const int*)  d_in[1];
  const float* W1     = (const float*)d_in[2];
  const float* tau_m  = (const float*)d_in[3];
  const float* tau_n  = (const float*)d_in[4];
  const float* mask   = (const float*)d_in[5];
  const float* W2     = (const float*)d_in[6];
  const float* b2     = (const float*)d_in[7];
  float* out = (float*)d_out;
  long long corrIdx = (long long)out_size - 2;   // layout: [loss, logits(B*T*2), correct, total]
  long long totIdx  = (long long)out_size - 1;

  prep_kernel<<<1, 640>>>(W1, tau_m, tau_n, mask, W2, b2, out, corrIdx, totIdx);
  snn_kernel<<<Bb, 32>>>(x);
  loss_kernel<<<(Bb*Tt + 255)/256, 256>>>(target, out, corrIdx);
}